// round 1
// baseline (speedup 1.0000x reference)
#include <cuda_runtime.h>

// Grouped MoE SwiGLU MLP, fp32 baseline.
//   h  = silu(x @ w1[e]^T) * (x @ w3[e]^T)   [T, H]
//   out = h @ w2[e]^T                         [T, D]
// Tokens are contiguous by expert; counts in d_in[4] (int32[E]).
// Rows >= sum(counts) must be zero.

#define E_CONST 8
#define D_CONST 1024
#define H_CONST 2816
#define T_MAX   16384

#define BM  128
#define BK  16
#define BNA 64     // phase A: N-tile per matrix (w1 and w3 simultaneously)
#define BNB 128    // phase B: N-tile
#define MAX_TILES ((T_MAX / BM) + E_CONST)   // 136

struct TileInfo { int row_start; int row_end; int expert; };
__device__ TileInfo g_tiles[MAX_TILES];
__device__ float g_h[(size_t)T_MAX * H_CONST];   // 184.5 MB scratch (device global: allowed)

// ---------------------------------------------------------------- setup
__global__ void setup_tiles_kernel(const int* __restrict__ counts) {
    if (threadIdx.x != 0 || blockIdx.x != 0) return;
    int off = 0, t = 0;
    for (int e = 0; e < E_CONST; ++e) {
        int c = counts[e];
        for (int s = 0; s < c && t < MAX_TILES; s += BM) {
            g_tiles[t].row_start = off + s;
            g_tiles[t].row_end   = off + (s + BM < c ? s + BM : c);
            g_tiles[t].expert    = e;
            ++t;
        }
        off += c;
    }
    for (; t < MAX_TILES; ++t) {
        g_tiles[t].row_start = 0; g_tiles[t].row_end = 0; g_tiles[t].expert = -1;
    }
}

// ---------------------------------------------------------------- zero output
__global__ void zero_out_kernel(float4* __restrict__ out, int n4) {
    int i = blockIdx.x * blockDim.x + threadIdx.x;
    if (i < n4) out[i] = make_float4(0.f, 0.f, 0.f, 0.f);
}

// ---------------------------------------------------------------- phase A
// Computes h = silu(x @ w1[e]^T) * (x @ w3[e]^T) for one [<=128 x 64] tile.
__global__ __launch_bounds__(256) void phaseA_kernel(
    const float* __restrict__ x,
    const float* __restrict__ w1,
    const float* __restrict__ w3)
{
    __shared__ float As [BK][BM  + 4];
    __shared__ float B1s[BK][BNA + 4];
    __shared__ float B3s[BK][BNA + 4];

    TileInfo tile = g_tiles[blockIdx.x];
    if (tile.expert < 0) return;
    const int row0    = tile.row_start;
    const int row_end = tile.row_end;
    const int n0      = blockIdx.y * BNA;
    const float* __restrict__ W1 = w1 + (size_t)tile.expert * H_CONST * D_CONST;
    const float* __restrict__ W3 = w3 + (size_t)tile.expert * H_CONST * D_CONST;

    const int tid = threadIdx.x;
    const int tx  = tid & 15;       // 0..15 -> N
    const int ty  = tid >> 4;       // 0..15 -> M

    // loader coordinates (float4 granularity)
    const int am0 = tid >> 2;         // A rows 0..63
    const int am1 = am0 + 64;         // A rows 64..127
    const int akq = (tid & 3) * 4;    // k offset
    const int bn  = tid >> 2;         // B rows (N dim) 0..63
    const int bkq = (tid & 3) * 4;

    float acc1[8][4] = {};
    float acc3[8][4] = {};
    float4 ra0, ra1, rb1, rb3;
    const float4 zero4 = make_float4(0.f, 0.f, 0.f, 0.f);

    // prefetch k-tile 0
    ra0 = (row0 + am0 < row_end)
        ? *(const float4*)&x[(size_t)(row0 + am0) * D_CONST + akq] : zero4;
    ra1 = (row0 + am1 < row_end)
        ? *(const float4*)&x[(size_t)(row0 + am1) * D_CONST + akq] : zero4;
    rb1 = *(const float4*)&W1[(size_t)(n0 + bn) * D_CONST + bkq];
    rb3 = *(const float4*)&W3[(size_t)(n0 + bn) * D_CONST + bkq];

    for (int k0 = 0; k0 < D_CONST; k0 += BK) {
        // commit prefetched tile to smem (transposed: [k][m]/[k][n])
        As [akq + 0][am0] = ra0.x; As [akq + 1][am0] = ra0.y;
        As [akq + 2][am0] = ra0.z; As [akq + 3][am0] = ra0.w;
        As [akq + 0][am1] = ra1.x; As [akq + 1][am1] = ra1.y;
        As [akq + 2][am1] = ra1.z; As [akq + 3][am1] = ra1.w;
        B1s[bkq + 0][bn ] = rb1.x; B1s[bkq + 1][bn ] = rb1.y;
        B1s[bkq + 2][bn ] = rb1.z; B1s[bkq + 3][bn ] = rb1.w;
        B3s[bkq + 0][bn ] = rb3.x; B3s[bkq + 1][bn ] = rb3.y;
        B3s[bkq + 2][bn ] = rb3.z; B3s[bkq + 3][bn ] = rb3.w;
        __syncthreads();

        const int kn = k0 + BK;
        if (kn < D_CONST) {   // issue next tile's global loads early (overlap compute)
            ra0 = (row0 + am0 < row_end)
                ? *(const float4*)&x[(size_t)(row0 + am0) * D_CONST + kn + akq] : zero4;
            ra1 = (row0 + am1 < row_end)
                ? *(const float4*)&x[(size_t)(row0 + am1) * D_CONST + kn + akq] : zero4;
            rb1 = *(const float4*)&W1[(size_t)(n0 + bn) * D_CONST + kn + bkq];
            rb3 = *(const float4*)&W3[(size_t)(n0 + bn) * D_CONST + kn + bkq];
        }

        #pragma unroll
        for (int kk = 0; kk < BK; ++kk) {
            float4 a0 = *(const float4*)&As [kk][ty * 4];
            float4 a1 = *(const float4*)&As [kk][64 + ty * 4];
            float4 b1 = *(const float4*)&B1s[kk][tx * 4];
            float4 b3 = *(const float4*)&B3s[kk][tx * 4];
            float av[8]  = {a0.x, a0.y, a0.z, a0.w, a1.x, a1.y, a1.z, a1.w};
            float b1v[4] = {b1.x, b1.y, b1.z, b1.w};
            float b3v[4] = {b3.x, b3.y, b3.z, b3.w};
            #pragma unroll
            for (int i = 0; i < 8; ++i) {
                #pragma unroll
                for (int j = 0; j < 4; ++j) {
                    acc1[i][j] += av[i] * b1v[j];
                    acc3[i][j] += av[i] * b3v[j];
                }
            }
        }
        __syncthreads();
    }

    // epilogue: SwiGLU, store h
    #pragma unroll
    for (int i = 0; i < 8; ++i) {
        const int r = row0 + ((i < 4) ? (ty * 4 + i) : (64 + ty * 4 + (i - 4)));
        if (r < row_end) {
            float4 o;
            {
                float z = acc1[i][0];
                o.x = (z / (1.f + __expf(-z))) * acc3[i][0];
            }
            {
                float z = acc1[i][1];
                o.y = (z / (1.f + __expf(-z))) * acc3[i][1];
            }
            {
                float z = acc1[i][2];
                o.z = (z / (1.f + __expf(-z))) * acc3[i][2];
            }
            {
                float z = acc1[i][3];
                o.w = (z / (1.f + __expf(-z))) * acc3[i][3];
            }
            *(float4*)&g_h[(size_t)r * H_CONST + n0 + tx * 4] = o;
        }
    }
}

// ---------------------------------------------------------------- phase B
// out = h @ w2[e]^T for one [<=128 x 128] tile.
__global__ __launch_bounds__(256) void phaseB_kernel(
    const float* __restrict__ w2,
    float* __restrict__ out)
{
    __shared__ float As[BK][BM  + 4];
    __shared__ float Bs[BK][BNB + 4];

    TileInfo tile = g_tiles[blockIdx.x];
    if (tile.expert < 0) return;
    const int row0    = tile.row_start;
    const int row_end = tile.row_end;
    const int n0      = blockIdx.y * BNB;
    const float* __restrict__ W2 = w2 + (size_t)tile.expert * D_CONST * H_CONST;

    const int tid = threadIdx.x;
    const int tx  = tid & 15;
    const int ty  = tid >> 4;

    const int am0 = tid >> 2;
    const int am1 = am0 + 64;
    const int akq = (tid & 3) * 4;
    const int bn0 = tid >> 2;
    const int bn1 = bn0 + 64;
    const int bkq = (tid & 3) * 4;

    float acc[8][8] = {};
    float4 ra0, ra1, rb0, rb1;
    const float4 zero4 = make_float4(0.f, 0.f, 0.f, 0.f);

    ra0 = (row0 + am0 < row_end)
        ? *(const float4*)&g_h[(size_t)(row0 + am0) * H_CONST + akq] : zero4;
    ra1 = (row0 + am1 < row_end)
        ? *(const float4*)&g_h[(size_t)(row0 + am1) * H_CONST + akq] : zero4;
    rb0 = *(const float4*)&W2[(size_t)(n0 + bn0) * H_CONST + bkq];
    rb1 = *(const float4*)&W2[(size_t)(n0 + bn1) * H_CONST + bkq];

    for (int k0 = 0; k0 < H_CONST; k0 += BK) {
        As[akq + 0][am0] = ra0.x; As[akq + 1][am0] = ra0.y;
        As[akq + 2][am0] = ra0.z; As[akq + 3][am0] = ra0.w;
        As[akq + 0][am1] = ra1.x; As[akq + 1][am1] = ra1.y;
        As[akq + 2][am1] = ra1.z; As[akq + 3][am1] = ra1.w;
        Bs[bkq + 0][bn0] = rb0.x; Bs[bkq + 1][bn0] = rb0.y;
        Bs[bkq + 2][bn0] = rb0.z; Bs[bkq + 3][bn0] = rb0.w;
        Bs[bkq + 0][bn1] = rb1.x; Bs[bkq + 1][bn1] = rb1.y;
        Bs[bkq + 2][bn1] = rb1.z; Bs[bkq + 3][bn1] = rb1.w;
        __syncthreads();

        const int kn = k0 + BK;
        if (kn < H_CONST) {
            ra0 = (row0 + am0 < row_end)
                ? *(const float4*)&g_h[(size_t)(row0 + am0) * H_CONST + kn + akq] : zero4;
            ra1 = (row0 + am1 < row_end)
                ? *(const float4*)&g_h[(size_t)(row0 + am1) * H_CONST + kn + akq] : zero4;
            rb0 = *(const float4*)&W2[(size_t)(n0 + bn0) * H_CONST + kn + bkq];
            rb1 = *(const float4*)&W2[(size_t)(n0 + bn1) * H_CONST + kn + bkq];
        }

        #pragma unroll
        for (int kk = 0; kk < BK; ++kk) {
            float4 a0 = *(const float4*)&As[kk][ty * 4];
            float4 a1 = *(const float4*)&As[kk][64 + ty * 4];
            float4 b0 = *(const float4*)&Bs[kk][tx * 4];
            float4 b1 = *(const float4*)&Bs[kk][64 + tx * 4];
            float av[8] = {a0.x, a0.y, a0.z, a0.w, a1.x, a1.y, a1.z, a1.w};
            float bv[8] = {b0.x, b0.y, b0.z, b0.w, b1.x, b1.y, b1.z, b1.w};
            #pragma unroll
            for (int i = 0; i < 8; ++i) {
                #pragma unroll
                for (int j = 0; j < 8; ++j) {
                    acc[i][j] += av[i] * bv[j];
                }
            }
        }
        __syncthreads();
    }

    #pragma unroll
    for (int i = 0; i < 8; ++i) {
        const int r = row0 + ((i < 4) ? (ty * 4 + i) : (64 + ty * 4 + (i - 4)));
        if (r < row_end) {
            float4 o0, o1;
            o0.x = acc[i][0]; o0.y = acc[i][1]; o0.z = acc[i][2]; o0.w = acc[i][3];
            o1.x = acc[i][4]; o1.y = acc[i][5]; o1.z = acc[i][6]; o1.w = acc[i][7];
            *(float4*)&out[(size_t)r * D_CONST + n0 + tx * 4]      = o0;
            *(float4*)&out[(size_t)r * D_CONST + n0 + 64 + tx * 4] = o1;
        }
    }
}

// ---------------------------------------------------------------- launcher
extern "C" void kernel_launch(void* const* d_in, const int* in_sizes, int n_in,
                              void* d_out, int out_size) {
    const float* x      = (const float*)d_in[0];
    const float* w1     = (const float*)d_in[1];
    const float* w2     = (const float*)d_in[2];
    const float* w3     = (const float*)d_in[3];
    const int*   counts = (const int*)  d_in[4];
    float* out = (float*)d_out;

    // zero the whole output (covers padding rows; valid rows overwritten by phase B)
    const int n4 = out_size / 4;
    zero_out_kernel<<<(n4 + 255) / 256, 256>>>((float4*)out, n4);

    setup_tiles_kernel<<<1, 32>>>(counts);

    dim3 ga(MAX_TILES, H_CONST / BNA);   // 136 x 44
    phaseA_kernel<<<ga, 256>>>(x, w1, w3);

    dim3 gb(MAX_TILES, D_CONST / BNB);   // 136 x 8
    phaseB_kernel<<<gb, 256>>>(w2, out);
}

// round 7
// speedup vs baseline: 2.7926x; 2.7926x over previous
#include <cuda_runtime.h>
#include <cuda_bf16.h>
#include <cstdint>

// Grouped MoE SwiGLU MLP via mma.sync bf16 hi/lo-split (plain sm_103 target —
// tcgen05 is rejected by this build's ptxas, so we use Ampere-style HMMA).
//   h  = silu(x @ w1[e]^T) * (x @ w3[e]^T)   [T, H]
//   out = h @ w2[e]^T                         [T, D]

#define E_CONST 8
#define D_CONST 1024
#define H_CONST 2816
#define T_MAX   16384
#define BM 128
#define MAX_TILES ((T_MAX / BM) + E_CONST)   // 136

#define KC     64         // K elems per smem chunk (64 bf16 = 128B rows)
#define STG    3          // pipeline stages

struct TileInfo { int row_start; int row_end; int expert; };
__device__ TileInfo g_tiles[MAX_TILES];

__device__ __nv_bfloat16 g_x_hi [(size_t)T_MAX * D_CONST];
__device__ __nv_bfloat16 g_x_lo [(size_t)T_MAX * D_CONST];
__device__ __nv_bfloat16 g_w1_hi[(size_t)E_CONST * H_CONST * D_CONST];
__device__ __nv_bfloat16 g_w1_lo[(size_t)E_CONST * H_CONST * D_CONST];
__device__ __nv_bfloat16 g_w3_hi[(size_t)E_CONST * H_CONST * D_CONST];
__device__ __nv_bfloat16 g_w3_lo[(size_t)E_CONST * H_CONST * D_CONST];
__device__ __nv_bfloat16 g_w2_hi[(size_t)E_CONST * D_CONST * H_CONST];
__device__ __nv_bfloat16 g_w2_lo[(size_t)E_CONST * D_CONST * H_CONST];
__device__ __nv_bfloat16 g_h_hi [(size_t)T_MAX * H_CONST];
__device__ __nv_bfloat16 g_h_lo [(size_t)T_MAX * H_CONST];

// ------------------------------------------------------------------ helpers
__device__ __forceinline__ uint32_t smem_u32(const void* p) {
    uint32_t a;
    asm("{ .reg .u64 t; cvta.to.shared.u64 t, %1; cvt.u32.u64 %0, t; }" : "=r"(a) : "l"(p));
    return a;
}
__device__ __forceinline__ void cp16(uint32_t dst, const void* src, uint32_t sz) {
    asm volatile("cp.async.cg.shared.global [%0], [%1], 16, %2;"
                 :: "r"(dst), "l"(src), "r"(sz) : "memory");
}
#define CP_COMMIT() asm volatile("cp.async.commit_group;" ::: "memory")
#define CP_WAIT1()  asm volatile("cp.async.wait_group 1;" ::: "memory")

__device__ __forceinline__ void ldm4(uint32_t a, uint32_t& r0, uint32_t& r1,
                                     uint32_t& r2, uint32_t& r3) {
    asm volatile("ldmatrix.sync.aligned.m8n8.x4.shared.b16 {%0,%1,%2,%3}, [%4];"
                 : "=r"(r0), "=r"(r1), "=r"(r2), "=r"(r3) : "r"(a));
}
__device__ __forceinline__ void mma_acc(float c[4], const uint32_t a[4], const uint32_t b[2]) {
    asm volatile("mma.sync.aligned.m16n8k16.row.col.f32.bf16.bf16.f32 "
                 "{%0,%1,%2,%3}, {%4,%5,%6,%7}, {%8,%9}, {%0,%1,%2,%3};"
                 : "+f"(c[0]), "+f"(c[1]), "+f"(c[2]), "+f"(c[3])
                 : "r"(a[0]), "r"(a[1]), "r"(a[2]), "r"(a[3]), "r"(b[0]), "r"(b[1]));
}

// ------------------------------------------------------------------ setup / zero / split
__global__ void setup_tiles_kernel(const int* __restrict__ counts) {
    if (threadIdx.x != 0 || blockIdx.x != 0) return;
    int off = 0, t = 0;
    for (int e = 0; e < E_CONST; ++e) {
        int c = counts[e];
        for (int s = 0; s < c && t < MAX_TILES; s += BM) {
            g_tiles[t].row_start = off + s;
            g_tiles[t].row_end   = off + (s + BM < c ? s + BM : c);
            g_tiles[t].expert    = e;
            ++t;
        }
        off += c;
    }
    for (; t < MAX_TILES; ++t) { g_tiles[t].row_start = 0; g_tiles[t].row_end = 0; g_tiles[t].expert = -1; }
}

__global__ void zero_out_kernel(float4* __restrict__ out, int n4) {
    int i = blockIdx.x * blockDim.x + threadIdx.x;
    if (i < n4) out[i] = make_float4(0.f, 0.f, 0.f, 0.f);
}

__global__ void split_kernel(const float4* __restrict__ src,
                             uint2* __restrict__ hi, uint2* __restrict__ lo, int n4) {
    int i = blockIdx.x * blockDim.x + threadIdx.x;
    if (i >= n4) return;
    float4 v = src[i];
    __nv_bfloat16 h0 = __float2bfloat16(v.x), h1 = __float2bfloat16(v.y);
    __nv_bfloat16 h2 = __float2bfloat16(v.z), h3 = __float2bfloat16(v.w);
    __nv_bfloat16 l0 = __float2bfloat16(v.x - __bfloat162float(h0));
    __nv_bfloat16 l1 = __float2bfloat16(v.y - __bfloat162float(h1));
    __nv_bfloat16 l2 = __float2bfloat16(v.z - __bfloat162float(h2));
    __nv_bfloat16 l3 = __float2bfloat16(v.w - __bfloat162float(h3));
    __nv_bfloat162 hp0 = __halves2bfloat162(h0, h1), hp1 = __halves2bfloat162(h2, h3);
    __nv_bfloat162 lp0 = __halves2bfloat162(l0, l1), lp1 = __halves2bfloat162(l2, l3);
    hi[i] = make_uint2(*(uint32_t*)&hp0, *(uint32_t*)&hp1);
    lo[i] = make_uint2(*(uint32_t*)&lp0, *(uint32_t*)&lp1);
}

// ------------------------------------------------------------------ phase A
// 128x64 output tile, dual (w1 and w3 share the A operand). SwiGLU fused in regs.
#define PA_A_TILE 16384                         // 128 rows x 128B
#define PA_B_TILE 8192                          // 64 rows x 128B
#define PA_STAGE  (2*PA_A_TILE + 4*PA_B_TILE)   // 64 KB
#define PA_SMEM   (STG * PA_STAGE)              // 192 KB
#define PA_NC     (D_CONST / KC)                // 16

__global__ __launch_bounds__(256, 1) void phaseA_kernel() {
    extern __shared__ char smem[];
    TileInfo tile = g_tiles[blockIdx.x];
    if (tile.expert < 0) return;
    const int row0 = tile.row_start;
    const int rows_valid = tile.row_end - row0;
    const int n0 = blockIdx.y * 64;

    const int tid = threadIdx.x, lane = tid & 31, wid = tid >> 5;
    const int wm = wid >> 1, wn = wid & 1;     // 4 x 2 warps; warp tile 32x32 per matrix
    const uint32_t sbase = smem_u32(smem);

    const size_t we = (size_t)tile.expert * H_CONST * D_CONST;
    const __nv_bfloat16* __restrict__ Ah  = g_x_hi  + (size_t)row0 * D_CONST;
    const __nv_bfloat16* __restrict__ Al  = g_x_lo  + (size_t)row0 * D_CONST;
    const __nv_bfloat16* __restrict__ B1h = g_w1_hi + we + (size_t)n0 * D_CONST;
    const __nv_bfloat16* __restrict__ B1l = g_w1_lo + we + (size_t)n0 * D_CONST;
    const __nv_bfloat16* __restrict__ B3h = g_w3_hi + we + (size_t)n0 * D_CONST;
    const __nv_bfloat16* __restrict__ B3l = g_w3_lo + we + (size_t)n0 * D_CONST;

    const int lq = tid & 7;          // 16B chunk within 128B row
    const int lr0 = tid >> 3;        // base row

    auto load_stage = [&](int s, int c) {
        const uint32_t st = sbase + s * PA_STAGE;
        const int k0 = c * KC;
        #pragma unroll
        for (int j = 0; j < 4; ++j) {               // A: 128 rows, hi+lo
            int r = lr0 + j * 32;
            uint32_t sz = (r < rows_valid) ? 16u : 0u;
            int rs = (r < rows_valid) ? r : 0;
            uint32_t d = st + r * 128 + ((lq * 16) ^ ((r & 7) << 4));
            const size_t go = (size_t)rs * D_CONST + k0 + lq * 8;
            cp16(d,             Ah + go, sz);
            cp16(d + PA_A_TILE, Al + go, sz);
        }
        #pragma unroll
        for (int j = 0; j < 2; ++j) {               // B: 64 rows x 4 arrays
            int r = lr0 + j * 32;
            uint32_t d = st + 2 * PA_A_TILE + r * 128 + ((lq * 16) ^ ((r & 7) << 4));
            const size_t go = (size_t)r * D_CONST + k0 + lq * 8;
            cp16(d,                 B1h + go, 16);
            cp16(d + PA_B_TILE,     B1l + go, 16);
            cp16(d + 2 * PA_B_TILE, B3h + go, 16);
            cp16(d + 3 * PA_B_TILE, B3l + go, 16);
        }
    };

    float acc1[2][4][4] = {};
    float acc3[2][4][4] = {};

    const int arow = lane & 15;
    const int akhi = (lane >> 4) << 4;        // 0 / 16 bytes
    const int brl  = lane & 7;
    const int bg   = lane >> 3;
    const int bkb  = (bg & 1) << 4;
    const int bno  = (bg >> 1) << 3;

    load_stage(0, 0); CP_COMMIT();
    load_stage(1, 1); CP_COMMIT();

    for (int c = 0; c < PA_NC; ++c) {
        CP_WAIT1();
        __syncthreads();
        if (c + 2 < PA_NC) load_stage((c + 2) % STG, c + 2);
        CP_COMMIT();

        const uint32_t st = sbase + (c % STG) * PA_STAGE;
        #pragma unroll
        for (int ks = 0; ks < 4; ++ks) {
            const int kb = ks * 32;
            uint32_t a_h[2][4], a_l[2][4];
            #pragma unroll
            for (int mt = 0; mt < 2; ++mt) {
                int r = wm * 32 + mt * 16 + arow;
                uint32_t ad = st + r * 128 + ((kb + akhi) ^ ((r & 7) << 4));
                ldm4(ad,             a_h[mt][0], a_h[mt][1], a_h[mt][2], a_h[mt][3]);
                ldm4(ad + PA_A_TILE, a_l[mt][0], a_l[mt][1], a_l[mt][2], a_l[mt][3]);
            }
            uint32_t b1h[4][2], b1l[4][2], b3h[4][2], b3l[4][2];
            #pragma unroll
            for (int p = 0; p < 2; ++p) {           // 2 n8-tile pairs per warp
                int nr = wn * 32 + p * 16 + bno + brl;
                uint32_t bb = st + 2 * PA_A_TILE + nr * 128 + ((kb + bkb) ^ ((nr & 7) << 4));
                ldm4(bb,                 b1h[2*p][0], b1h[2*p][1], b1h[2*p+1][0], b1h[2*p+1][1]);
                ldm4(bb + PA_B_TILE,     b1l[2*p][0], b1l[2*p][1], b1l[2*p+1][0], b1l[2*p+1][1]);
                ldm4(bb + 2 * PA_B_TILE, b3h[2*p][0], b3h[2*p][1], b3h[2*p+1][0], b3h[2*p+1][1]);
                ldm4(bb + 3 * PA_B_TILE, b3l[2*p][0], b3l[2*p][1], b3l[2*p+1][0], b3l[2*p+1][1]);
            }
            #pragma unroll
            for (int mt = 0; mt < 2; ++mt) {
                #pragma unroll
                for (int nt = 0; nt < 4; ++nt) {
                    mma_acc(acc1[mt][nt], a_h[mt], b1h[nt]);
                    mma_acc(acc1[mt][nt], a_h[mt], b1l[nt]);
                    mma_acc(acc1[mt][nt], a_l[mt], b1h[nt]);
                    mma_acc(acc3[mt][nt], a_h[mt], b3h[nt]);
                    mma_acc(acc3[mt][nt], a_h[mt], b3l[nt]);
                    mma_acc(acc3[mt][nt], a_l[mt], b3h[nt]);
                }
            }
        }
    }

    // epilogue: SwiGLU in regs, write h as bf16 hi/lo
    const int l4 = lane >> 2, l2 = (lane & 3) * 2;
    #pragma unroll
    for (int mt = 0; mt < 2; ++mt) {
        #pragma unroll
        for (int nt = 0; nt < 4; ++nt) {
            const int col = n0 + wn * 32 + nt * 8 + l2;
            #pragma unroll
            for (int half = 0; half < 2; ++half) {
                int rl = wm * 32 + mt * 16 + l4 + half * 8;
                if (rl < rows_valid) {
                    float z0 = acc1[mt][nt][half * 2 + 0];
                    float z1 = acc1[mt][nt][half * 2 + 1];
                    float v0 = (z0 / (1.f + __expf(-z0))) * acc3[mt][nt][half * 2 + 0];
                    float v1 = (z1 / (1.f + __expf(-z1))) * acc3[mt][nt][half * 2 + 1];
                    __nv_bfloat16 h0 = __float2bfloat16(v0), h1 = __float2bfloat16(v1);
                    __nv_bfloat16 o0 = __float2bfloat16(v0 - __bfloat162float(h0));
                    __nv_bfloat16 o1 = __float2bfloat16(v1 - __bfloat162float(h1));
                    size_t go = (size_t)(row0 + rl) * H_CONST + col;
                    *(__nv_bfloat162*)(g_h_hi + go) = __halves2bfloat162(h0, h1);
                    *(__nv_bfloat162*)(g_h_lo + go) = __halves2bfloat162(o0, o1);
                }
            }
        }
    }
}

// ------------------------------------------------------------------ phase B
// 128x128 output tile: out = h @ w2^T
#define PB_TILE  16384                          // 128 rows x 128B
#define PB_STAGE (4 * PB_TILE)                  // 64 KB
#define PB_SMEM  (STG * PB_STAGE)               // 192 KB
#define PB_NC    (H_CONST / KC)                 // 44

__global__ __launch_bounds__(256, 1) void phaseB_kernel(float* __restrict__ out) {
    extern __shared__ char smem[];
    TileInfo tile = g_tiles[blockIdx.x];
    if (tile.expert < 0) return;
    const int row0 = tile.row_start;
    const int rows_valid = tile.row_end - row0;
    const int n0 = blockIdx.y * 128;

    const int tid = threadIdx.x, lane = tid & 31, wid = tid >> 5;
    const int wm = wid >> 1, wn = wid & 1;     // warp tile 32 x 64
    const uint32_t sbase = smem_u32(smem);

    const size_t we = (size_t)tile.expert * D_CONST * H_CONST;
    const __nv_bfloat16* __restrict__ Ah = g_h_hi  + (size_t)row0 * H_CONST;
    const __nv_bfloat16* __restrict__ Al = g_h_lo  + (size_t)row0 * H_CONST;
    const __nv_bfloat16* __restrict__ Bh = g_w2_hi + we + (size_t)n0 * H_CONST;
    const __nv_bfloat16* __restrict__ Bl = g_w2_lo + we + (size_t)n0 * H_CONST;

    const int lq = tid & 7;
    const int lr0 = tid >> 3;

    auto load_stage = [&](int s, int c) {
        const uint32_t st = sbase + s * PB_STAGE;
        const int k0 = c * KC;
        #pragma unroll
        for (int j = 0; j < 4; ++j) {
            int r = lr0 + j * 32;
            uint32_t sz = (r < rows_valid) ? 16u : 0u;
            int rs = (r < rows_valid) ? r : 0;
            uint32_t swo = r * 128 + ((lq * 16) ^ ((r & 7) << 4));
            const size_t goA = (size_t)rs * H_CONST + k0 + lq * 8;
            const size_t goB = (size_t)r  * H_CONST + k0 + lq * 8;
            cp16(st + swo,               Ah + goA, sz);
            cp16(st + PB_TILE + swo,     Al + goA, sz);
            cp16(st + 2 * PB_TILE + swo, Bh + goB, 16);
            cp16(st + 3 * PB_TILE + swo, Bl + goB, 16);
        }
    };

    float acc[2][8][4] = {};

    const int arow = lane & 15;
    const int akhi = (lane >> 4) << 4;
    const int brl  = lane & 7;
    const int bg   = lane >> 3;
    const int bkb  = (bg & 1) << 4;
    const int bno  = (bg >> 1) << 3;

    load_stage(0, 0); CP_COMMIT();
    load_stage(1, 1); CP_COMMIT();

    for (int c = 0; c < PB_NC; ++c) {
        CP_WAIT1();
        __syncthreads();
        if (c + 2 < PB_NC) load_stage((c + 2) % STG, c + 2);
        CP_COMMIT();

        const uint32_t st = sbase + (c % STG) * PB_STAGE;
        #pragma unroll
        for (int ks = 0; ks < 4; ++ks) {
            const int kb = ks * 32;
            uint32_t a_h[2][4], a_l[2][4];
            #pragma unroll
            for (int mt = 0; mt < 2; ++mt) {
                int r = wm * 32 + mt * 16 + arow;
                uint32_t ad = st + r * 128 + ((kb + akhi) ^ ((r & 7) << 4));
                ldm4(ad,           a_h[mt][0], a_h[mt][1], a_h[mt][2], a_h[mt][3]);
                ldm4(ad + PB_TILE, a_l[mt][0], a_l[mt][1], a_l[mt][2], a_l[mt][3]);
            }
            uint32_t bh[8][2], bl[8][2];
            #pragma unroll
            for (int p = 0; p < 4; ++p) {
                int nr = wn * 64 + p * 16 + bno + brl;
                uint32_t bb = st + 2 * PB_TILE + nr * 128 + ((kb + bkb) ^ ((nr & 7) << 4));
                ldm4(bb,           bh[2*p][0], bh[2*p][1], bh[2*p+1][0], bh[2*p+1][1]);
                ldm4(bb + PB_TILE, bl[2*p][0], bl[2*p][1], bl[2*p+1][0], bl[2*p+1][1]);
            }
            #pragma unroll
            for (int mt = 0; mt < 2; ++mt) {
                #pragma unroll
                for (int nt = 0; nt < 8; ++nt) {
                    mma_acc(acc[mt][nt], a_h[mt], bh[nt]);
                    mma_acc(acc[mt][nt], a_h[mt], bl[nt]);
                    mma_acc(acc[mt][nt], a_l[mt], bh[nt]);
                }
            }
        }
    }

    const int l4 = lane >> 2, l2 = (lane & 3) * 2;
    #pragma unroll
    for (int mt = 0; mt < 2; ++mt) {
        #pragma unroll
        for (int nt = 0; nt < 8; ++nt) {
            const int col = n0 + wn * 64 + nt * 8 + l2;
            #pragma unroll
            for (int half = 0; half < 2; ++half) {
                int rl = wm * 32 + mt * 16 + l4 + half * 8;
                if (rl < rows_valid) {
                    float2 v;
                    v.x = acc[mt][nt][half * 2 + 0];
                    v.y = acc[mt][nt][half * 2 + 1];
                    *(float2*)(out + (size_t)(row0 + rl) * D_CONST + col) = v;
                }
            }
        }
    }
}

// ------------------------------------------------------------------ launcher
extern "C" void kernel_launch(void* const* d_in, const int* in_sizes, int n_in,
                              void* d_out, int out_size) {
    const float* x      = (const float*)d_in[0];
    const float* w1     = (const float*)d_in[1];
    const float* w2     = (const float*)d_in[2];
    const float* w3     = (const float*)d_in[3];
    const int*   counts = (const int*)  d_in[4];
    float* out = (float*)d_out;

    cudaFuncSetAttribute(phaseA_kernel, cudaFuncAttributeMaxDynamicSharedMemorySize, PA_SMEM);
    cudaFuncSetAttribute(phaseB_kernel, cudaFuncAttributeMaxDynamicSharedMemorySize, PB_SMEM);

    const int n4 = out_size / 4;
    zero_out_kernel<<<(n4 + 255) / 256, 256>>>((float4*)out, n4);
    setup_tiles_kernel<<<1, 32>>>(counts);

    {
        __nv_bfloat16 *xh, *xl, *w1h, *w1l, *w2h, *w2l, *w3h, *w3l;
        cudaGetSymbolAddress((void**)&xh,  g_x_hi);  cudaGetSymbolAddress((void**)&xl,  g_x_lo);
        cudaGetSymbolAddress((void**)&w1h, g_w1_hi); cudaGetSymbolAddress((void**)&w1l, g_w1_lo);
        cudaGetSymbolAddress((void**)&w2h, g_w2_hi); cudaGetSymbolAddress((void**)&w2l, g_w2_lo);
        cudaGetSymbolAddress((void**)&w3h, g_w3_hi); cudaGetSymbolAddress((void**)&w3l, g_w3_lo);

        int nx4 = (T_MAX * D_CONST) / 4;
        split_kernel<<<(nx4 + 255) / 256, 256>>>((const float4*)x, (uint2*)xh, (uint2*)xl, nx4);
        int nw4 = (E_CONST * H_CONST * D_CONST) / 4;
        split_kernel<<<(nw4 + 255) / 256, 256>>>((const float4*)w1, (uint2*)w1h, (uint2*)w1l, nw4);
        split_kernel<<<(nw4 + 255) / 256, 256>>>((const float4*)w3, (uint2*)w3h, (uint2*)w3l, nw4);
        split_kernel<<<(nw4 + 255) / 256, 256>>>((const float4*)w2, (uint2*)w2h, (uint2*)w2l, nw4);
    }

    dim3 ga(MAX_TILES, H_CONST / 64);    // 136 x 44
    phaseA_kernel<<<ga, 256, PA_SMEM>>>();

    dim3 gb(MAX_TILES, D_CONST / 128);   // 136 x 8
    phaseB_kernel<<<gb, 256, PB_SMEM>>>(out);
}

// round 8
// speedup vs baseline: 7.3182x; 2.6206x over previous
#include <cuda_runtime.h>
#include <cuda_fp16.h>
#include <cstdint>

// Grouped MoE SwiGLU MLP via single-pass fp16 mma.sync (plain sm_103 target).
//   h  = silu(x @ w1[e]^T) * (x @ w3[e]^T)   [T, H]
//   out = h @ w2[e]^T                         [T, D]
// fp16 quantization error ~1.4e-4 rms/elem -> ~4-5e-4 end-to-end vs 1e-3 gate.

#define E_CONST 8
#define D_CONST 1024
#define H_CONST 2816
#define T_MAX   16384
#define BM 128
#define MAX_TILES ((T_MAX / BM) + E_CONST)   // 136

#define KC  64        // K elems per smem chunk (64 fp16 = 128B rows)
#define STG 3         // pipeline stages

struct TileInfo { int row_start; int row_end; int expert; };
__device__ TileInfo g_tiles[MAX_TILES];

__device__ __half g_x [(size_t)T_MAX * D_CONST];
__device__ __half g_w1[(size_t)E_CONST * H_CONST * D_CONST];
__device__ __half g_w3[(size_t)E_CONST * H_CONST * D_CONST];
__device__ __half g_w2[(size_t)E_CONST * D_CONST * H_CONST];
__device__ __half g_h [(size_t)T_MAX * H_CONST];

// ------------------------------------------------------------------ helpers
__device__ __forceinline__ uint32_t smem_u32(const void* p) {
    uint32_t a;
    asm("{ .reg .u64 t; cvta.to.shared.u64 t, %1; cvt.u32.u64 %0, t; }" : "=r"(a) : "l"(p));
    return a;
}
__device__ __forceinline__ void cp16(uint32_t dst, const void* src, uint32_t sz) {
    asm volatile("cp.async.cg.shared.global [%0], [%1], 16, %2;"
                 :: "r"(dst), "l"(src), "r"(sz) : "memory");
}
#define CP_COMMIT() asm volatile("cp.async.commit_group;" ::: "memory")
#define CP_WAIT1()  asm volatile("cp.async.wait_group 1;" ::: "memory")
#define CP_WAIT0()  asm volatile("cp.async.wait_group 0;" ::: "memory")

__device__ __forceinline__ void ldm4(uint32_t a, uint32_t& r0, uint32_t& r1,
                                     uint32_t& r2, uint32_t& r3) {
    asm volatile("ldmatrix.sync.aligned.m8n8.x4.shared.b16 {%0,%1,%2,%3}, [%4];"
                 : "=r"(r0), "=r"(r1), "=r"(r2), "=r"(r3) : "r"(a));
}
__device__ __forceinline__ void mma_acc(float c[4], const uint32_t a[4], const uint32_t b[2]) {
    asm volatile("mma.sync.aligned.m16n8k16.row.col.f32.f16.f16.f32 "
                 "{%0,%1,%2,%3}, {%4,%5,%6,%7}, {%8,%9}, {%0,%1,%2,%3};"
                 : "+f"(c[0]), "+f"(c[1]), "+f"(c[2]), "+f"(c[3])
                 : "r"(a[0]), "r"(a[1]), "r"(a[2]), "r"(a[3]), "r"(b[0]), "r"(b[1]));
}

// ------------------------------------------------------------------ setup / zero / convert
__global__ void setup_tiles_kernel(const int* __restrict__ counts) {
    if (threadIdx.x != 0 || blockIdx.x != 0) return;
    int off = 0, t = 0;
    for (int e = 0; e < E_CONST; ++e) {
        int c = counts[e];
        for (int s = 0; s < c && t < MAX_TILES; s += BM) {
            g_tiles[t].row_start = off + s;
            g_tiles[t].row_end   = off + (s + BM < c ? s + BM : c);
            g_tiles[t].expert    = e;
            ++t;
        }
        off += c;
    }
    for (; t < MAX_TILES; ++t) { g_tiles[t].row_start = 0; g_tiles[t].row_end = 0; g_tiles[t].expert = -1; }
}

__global__ void zero_out_kernel(float4* __restrict__ out, int n4) {
    int i = blockIdx.x * blockDim.x + threadIdx.x;
    if (i < n4) out[i] = make_float4(0.f, 0.f, 0.f, 0.f);
}

__global__ void cvt_kernel(const float4* __restrict__ src, uint2* __restrict__ dst, int n4) {
    int i = blockIdx.x * blockDim.x + threadIdx.x;
    if (i >= n4) return;
    float4 v = src[i];
    __half2 a = __floats2half2_rn(v.x, v.y);
    __half2 b = __floats2half2_rn(v.z, v.w);
    dst[i] = make_uint2(*(uint32_t*)&a, *(uint32_t*)&b);
}

// ------------------------------------------------------------------ phase A
// CTA tile 128x64. Warps 0-3: S1 = x@w1^T (rows wid*32..); warps 4-7: S3 = x@w3^T.
// SwiGLU fused via smem exchange.
#define PA_A_TILE 16384                       // 128 rows x 128B
#define PA_B_TILE 8192                        // 64 rows x 128B
#define PA_STAGE  (PA_A_TILE + 2*PA_B_TILE)   // 32 KB
#define PA_SMEM   (STG * PA_STAGE)            // 96 KB
#define PA_NC     (D_CONST / KC)              // 16

__global__ __launch_bounds__(256, 2) void phaseA_kernel() {
    extern __shared__ char smem[];
    TileInfo tile = g_tiles[blockIdx.x];
    if (tile.expert < 0) return;
    const int row0 = tile.row_start;
    const int rows_valid = tile.row_end - row0;
    const int n0 = blockIdx.y * 64;

    const int tid = threadIdx.x, lane = tid & 31, wid = tid >> 5;
    const int wm = wid & 3;                  // row group (32 rows)
    const bool is3 = wid >= 4;               // matrix selector
    const uint32_t sbase = smem_u32(smem);

    const size_t we = (size_t)tile.expert * H_CONST * D_CONST;
    const __half* __restrict__ A  = g_x  + (size_t)row0 * D_CONST;
    const __half* __restrict__ B1 = g_w1 + we + (size_t)n0 * D_CONST;
    const __half* __restrict__ B3 = g_w3 + we + (size_t)n0 * D_CONST;

    const int lq = tid & 7;          // 16B chunk within 128B row
    const int lr0 = tid >> 3;        // base row (0..31)

    auto load_stage = [&](int s, int c) {
        const uint32_t st = sbase + s * PA_STAGE;
        const int k0 = c * KC;
        #pragma unroll
        for (int j = 0; j < 4; ++j) {               // A: 128 rows
            int r = lr0 + j * 32;
            uint32_t sz = (r < rows_valid) ? 16u : 0u;
            int rs = (r < rows_valid) ? r : 0;
            uint32_t d = st + r * 128 + ((lq * 16) ^ ((r & 7) << 4));
            cp16(d, A + (size_t)rs * D_CONST + k0 + lq * 8, sz);
        }
        #pragma unroll
        for (int j = 0; j < 2; ++j) {               // B1, B3: 64 rows each
            int r = lr0 + j * 32;
            uint32_t d = st + PA_A_TILE + r * 128 + ((lq * 16) ^ ((r & 7) << 4));
            const size_t go = (size_t)r * D_CONST + k0 + lq * 8;
            cp16(d,             B1 + go, 16);
            cp16(d + PA_B_TILE, B3 + go, 16);
        }
    };

    float acc[2][8][4] = {};     // warp tile 32 x 64

    const int arow = lane & 15;
    const int akhi = (lane >> 4) << 4;        // 0 / 16 bytes
    const int brl  = lane & 7;
    const int bg   = lane >> 3;
    const int bkb  = (bg & 1) << 4;
    const int bno  = (bg >> 1) << 3;
    const uint32_t boff = PA_A_TILE + (is3 ? PA_B_TILE : 0u);

    load_stage(0, 0); CP_COMMIT();
    load_stage(1, 1); CP_COMMIT();

    for (int c = 0; c < PA_NC; ++c) {
        CP_WAIT1();
        __syncthreads();
        if (c + 2 < PA_NC) load_stage((c + 2) % STG, c + 2);
        CP_COMMIT();

        const uint32_t st = sbase + (c % STG) * PA_STAGE;
        #pragma unroll
        for (int ks = 0; ks < 4; ++ks) {
            const int kb = ks * 32;
            uint32_t a[2][4];
            #pragma unroll
            for (int mt = 0; mt < 2; ++mt) {
                int r = wm * 32 + mt * 16 + arow;
                uint32_t ad = st + r * 128 + ((kb + akhi) ^ ((r & 7) << 4));
                ldm4(ad, a[mt][0], a[mt][1], a[mt][2], a[mt][3]);
            }
            uint32_t b[8][2];
            #pragma unroll
            for (int p = 0; p < 4; ++p) {
                int nr = p * 16 + bno + brl;
                uint32_t bb = st + boff + nr * 128 + ((kb + bkb) ^ ((nr & 7) << 4));
                ldm4(bb, b[2*p][0], b[2*p][1], b[2*p+1][0], b[2*p+1][1]);
            }
            #pragma unroll
            for (int mt = 0; mt < 2; ++mt)
                #pragma unroll
                for (int nt = 0; nt < 8; ++nt)
                    mma_acc(acc[mt][nt], a[mt], b[nt]);
        }
        __syncthreads();
    }

    // epilogue: exchange S3 via smem, fuse SwiGLU, store h fp16
    CP_WAIT0();
    __syncthreads();
    float* s3 = (float*)smem;    // 128 x 64 fp32 = 32 KB
    const int l4 = lane >> 2, l2 = (lane & 3) * 2;

    if (is3) {
        #pragma unroll
        for (int mt = 0; mt < 2; ++mt)
            #pragma unroll
            for (int nt = 0; nt < 8; ++nt)
                #pragma unroll
                for (int half = 0; half < 2; ++half) {
                    int r = wm * 32 + mt * 16 + l4 + half * 8;
                    int cidx = nt * 8 + l2;
                    s3[r * 64 + cidx + 0] = acc[mt][nt][half * 2 + 0];
                    s3[r * 64 + cidx + 1] = acc[mt][nt][half * 2 + 1];
                }
    }
    __syncthreads();
    if (!is3) {
        #pragma unroll
        for (int mt = 0; mt < 2; ++mt)
            #pragma unroll
            for (int nt = 0; nt < 8; ++nt)
                #pragma unroll
                for (int half = 0; half < 2; ++half) {
                    int r = wm * 32 + mt * 16 + l4 + half * 8;
                    if (r < rows_valid) {
                        int cidx = nt * 8 + l2;
                        float z0 = acc[mt][nt][half * 2 + 0];
                        float z1 = acc[mt][nt][half * 2 + 1];
                        float v0 = (z0 / (1.f + __expf(-z0))) * s3[r * 64 + cidx + 0];
                        float v1 = (z1 / (1.f + __expf(-z1))) * s3[r * 64 + cidx + 1];
                        __half2 hv = __floats2half2_rn(v0, v1);
                        *(__half2*)(g_h + (size_t)(row0 + r) * H_CONST + n0 + cidx) = hv;
                    }
                }
    }
}

// ------------------------------------------------------------------ phase B
// CTA tile 128x128: out = h @ w2^T. Warp tile 32x64.
#define PB_TILE  16384                        // 128 rows x 128B
#define PB_STAGE (2 * PB_TILE)                // 32 KB
#define PB_SMEM  (STG * PB_STAGE)             // 96 KB
#define PB_NC    (H_CONST / KC)               // 44

__global__ __launch_bounds__(256, 2) void phaseB_kernel(float* __restrict__ out) {
    extern __shared__ char smem[];
    TileInfo tile = g_tiles[blockIdx.x];
    if (tile.expert < 0) return;
    const int row0 = tile.row_start;
    const int rows_valid = tile.row_end - row0;
    const int n0 = blockIdx.y * 128;

    const int tid = threadIdx.x, lane = tid & 31, wid = tid >> 5;
    const int wm = wid >> 1, wn = wid & 1;
    const uint32_t sbase = smem_u32(smem);

    const size_t we = (size_t)tile.expert * D_CONST * H_CONST;
    const __half* __restrict__ A = g_h  + (size_t)row0 * H_CONST;
    const __half* __restrict__ B = g_w2 + we + (size_t)n0 * H_CONST;

    const int lq = tid & 7;
    const int lr0 = tid >> 3;

    auto load_stage = [&](int s, int c) {
        const uint32_t st = sbase + s * PB_STAGE;
        const int k0 = c * KC;
        #pragma unroll
        for (int j = 0; j < 4; ++j) {
            int r = lr0 + j * 32;
            uint32_t sz = (r < rows_valid) ? 16u : 0u;
            int rs = (r < rows_valid) ? r : 0;
            uint32_t swo = r * 128 + ((lq * 16) ^ ((r & 7) << 4));
            cp16(st + swo,           A + (size_t)rs * H_CONST + k0 + lq * 8, sz);
            cp16(st + PB_TILE + swo, B + (size_t)r  * H_CONST + k0 + lq * 8, 16);
        }
    };

    float acc[2][8][4] = {};

    const int arow = lane & 15;
    const int akhi = (lane >> 4) << 4;
    const int brl  = lane & 7;
    const int bg   = lane >> 3;
    const int bkb  = (bg & 1) << 4;
    const int bno  = (bg >> 1) << 3;

    load_stage(0, 0); CP_COMMIT();
    load_stage(1, 1); CP_COMMIT();

    for (int c = 0; c < PB_NC; ++c) {
        CP_WAIT1();
        __syncthreads();
        if (c + 2 < PB_NC) load_stage((c + 2) % STG, c + 2);
        CP_COMMIT();

        const uint32_t st = sbase + (c % STG) * PB_STAGE;
        #pragma unroll
        for (int ks = 0; ks < 4; ++ks) {
            const int kb = ks * 32;
            uint32_t a[2][4];
            #pragma unroll
            for (int mt = 0; mt < 2; ++mt) {
                int r = wm * 32 + mt * 16 + arow;
                uint32_t ad = st + r * 128 + ((kb + akhi) ^ ((r & 7) << 4));
                ldm4(ad, a[mt][0], a[mt][1], a[mt][2], a[mt][3]);
            }
            uint32_t b[8][2];
            #pragma unroll
            for (int p = 0; p < 4; ++p) {
                int nr = wn * 64 + p * 16 + bno + brl;
                uint32_t bb = st + PB_TILE + nr * 128 + ((kb + bkb) ^ ((nr & 7) << 4));
                ldm4(bb, b[2*p][0], b[2*p][1], b[2*p+1][0], b[2*p+1][1]);
            }
            #pragma unroll
            for (int mt = 0; mt < 2; ++mt)
                #pragma unroll
                for (int nt = 0; nt < 8; ++nt)
                    mma_acc(acc[mt][nt], a[mt], b[nt]);
        }
        __syncthreads();
    }

    const int l4 = lane >> 2, l2 = (lane & 3) * 2;
    #pragma unroll
    for (int mt = 0; mt < 2; ++mt)
        #pragma unroll
        for (int nt = 0; nt < 8; ++nt) {
            const int col = n0 + wn * 64 + nt * 8 + l2;
            #pragma unroll
            for (int half = 0; half < 2; ++half) {
                int rl = wm * 32 + mt * 16 + l4 + half * 8;
                if (rl < rows_valid) {
                    float2 v;
                    v.x = acc[mt][nt][half * 2 + 0];
                    v.y = acc[mt][nt][half * 2 + 1];
                    *(float2*)(out + (size_t)(row0 + rl) * D_CONST + col) = v;
                }
            }
        }
}

// ------------------------------------------------------------------ launcher
extern "C" void kernel_launch(void* const* d_in, const int* in_sizes, int n_in,
                              void* d_out, int out_size) {
    const float* x      = (const float*)d_in[0];
    const float* w1     = (const float*)d_in[1];
    const float* w2     = (const float*)d_in[2];
    const float* w3     = (const float*)d_in[3];
    const int*   counts = (const int*)  d_in[4];
    float* out = (float*)d_out;

    cudaFuncSetAttribute(phaseA_kernel, cudaFuncAttributeMaxDynamicSharedMemorySize, PA_SMEM);
    cudaFuncSetAttribute(phaseB_kernel, cudaFuncAttributeMaxDynamicSharedMemorySize, PB_SMEM);

    const int n4 = out_size / 4;
    zero_out_kernel<<<(n4 + 255) / 256, 256>>>((float4*)out, n4);
    setup_tiles_kernel<<<1, 32>>>(counts);

    {
        __half *xp, *w1p, *w2p, *w3p;
        cudaGetSymbolAddress((void**)&xp,  g_x);
        cudaGetSymbolAddress((void**)&w1p, g_w1);
        cudaGetSymbolAddress((void**)&w2p, g_w2);
        cudaGetSymbolAddress((void**)&w3p, g_w3);

        int nx4 = (T_MAX * D_CONST) / 4;
        cvt_kernel<<<(nx4 + 255) / 256, 256>>>((const float4*)x, (uint2*)xp, nx4);
        int nw4 = (E_CONST * H_CONST * D_CONST) / 4;
        cvt_kernel<<<(nw4 + 255) / 256, 256>>>((const float4*)w1, (uint2*)w1p, nw4);
        cvt_kernel<<<(nw4 + 255) / 256, 256>>>((const float4*)w3, (uint2*)w3p, nw4);
        cvt_kernel<<<(nw4 + 255) / 256, 256>>>((const float4*)w2, (uint2*)w2p, nw4);
    }

    dim3 ga(MAX_TILES, H_CONST / 64);    // 136 x 44
    phaseA_kernel<<<ga, 256, PA_SMEM>>>();

    dim3 gb(MAX_TILES, D_CONST / 128);   // 136 x 8
    phaseB_kernel<<<gb, 256, PB_SMEM>>>(out);
}